// round 2
// baseline (speedup 1.0000x reference)
#include <cuda_runtime.h>
#include <cuda_bf16.h>

#define N_NODES 100000
#define N_EDGES 3200000
#define IN_CH   128
#define HID     16

// ---------------- device scratch (no allocation allowed) ----------------
__device__ __align__(16) float g_deg [N_NODES];
__device__ __align__(16) float g_dinv[N_NODES];
__device__ __align__(16) float g_hs  [N_NODES * HID];   // dinv-scaled features (message source)
__device__ __align__(16) float g_acc [N_NODES * HID];   // segment-sum accumulator (init = self loop)

// ---------------- kernels ----------------

__global__ void k_init_deg(int n) {
    int i = blockIdx.x * blockDim.x + threadIdx.x;
    if (i < n) g_deg[i] = 1.0f;   // self-loop
}

__global__ void k_count(const int* __restrict__ col, int e) {
    int i = blockIdx.x * blockDim.x + threadIdx.x;
    if (i < e) atomicAdd(&g_deg[col[i]], 1.0f);
}

__global__ void k_dinv(int n) {
    int i = blockIdx.x * blockDim.x + threadIdx.x;
    if (i < n) g_dinv[i] = rsqrtf(g_deg[i]);   // deg >= 1 always (self loop)
}

// hs = dinv * (x @ W1); acc = hs  (self-loop term pre-seeded)
__global__ void k_mm1(const float* __restrict__ x, const float* __restrict__ W1, int n) {
    __shared__ float Ws[IN_CH * HID];
    for (int t = threadIdx.x; t < IN_CH * HID; t += blockDim.x) Ws[t] = W1[t];
    __syncthreads();

    int i = blockIdx.x * blockDim.x + threadIdx.x;
    if (i >= n) return;

    float acc[HID];
#pragma unroll
    for (int j = 0; j < HID; j++) acc[j] = 0.0f;

    const float4* xr = (const float4*)(x + (size_t)i * IN_CH);
#pragma unroll 4
    for (int k4 = 0; k4 < IN_CH / 4; k4++) {
        float4 xv = xr[k4];
        const float* w = &Ws[(k4 * 4) * HID];
#pragma unroll
        for (int j = 0; j < HID; j++) acc[j] += xv.x * w[j];
#pragma unroll
        for (int j = 0; j < HID; j++) acc[j] += xv.y * w[HID + j];
#pragma unroll
        for (int j = 0; j < HID; j++) acc[j] += xv.z * w[2 * HID + j];
#pragma unroll
        for (int j = 0; j < HID; j++) acc[j] += xv.w * w[3 * HID + j];
    }

    float d = g_dinv[i];
    float4* hsp  = (float4*)&g_hs [(size_t)i * HID];
    float4* accp = (float4*)&g_acc[(size_t)i * HID];
#pragma unroll
    for (int q = 0; q < 4; q++) {
        float4 v;
        v.x = d * acc[4 * q + 0];
        v.y = d * acc[4 * q + 1];
        v.z = d * acc[4 * q + 2];
        v.w = d * acc[4 * q + 3];
        hsp[q]  = v;
        accp[q] = v;
    }
}

// per-edge: acc[col] += hs[row]  (16 floats = 4x red.global.add.v4.f32)
__global__ void k_scatter(const int* __restrict__ row, const int* __restrict__ col, int e) {
    int i = blockIdx.x * blockDim.x + threadIdx.x;
    if (i >= e) return;
    int r = row[i];
    int c = col[i];
    const float4* src = (const float4*)&g_hs[(size_t)r * HID];
    float4 v0 = src[0], v1 = src[1], v2 = src[2], v3 = src[3];
    float* dst = &g_acc[(size_t)c * HID];
    asm volatile("red.global.add.v4.f32 [%0], {%1,%2,%3,%4};"
                 :: "l"(dst +  0), "f"(v0.x), "f"(v0.y), "f"(v0.z), "f"(v0.w) : "memory");
    asm volatile("red.global.add.v4.f32 [%0], {%1,%2,%3,%4};"
                 :: "l"(dst +  4), "f"(v1.x), "f"(v1.y), "f"(v1.z), "f"(v1.w) : "memory");
    asm volatile("red.global.add.v4.f32 [%0], {%1,%2,%3,%4};"
                 :: "l"(dst +  8), "f"(v2.x), "f"(v2.y), "f"(v2.z), "f"(v2.w) : "memory");
    asm volatile("red.global.add.v4.f32 [%0], {%1,%2,%3,%4};"
                 :: "l"(dst + 12), "f"(v3.x), "f"(v3.y), "f"(v3.z), "f"(v3.w) : "memory");
}

// h1 = relu(dinv*acc + b1);  hs2 = dinv*(h1 @ W2);  acc = hs2
__global__ void k_mid(const float* __restrict__ W2, const float* __restrict__ b1, int n) {
    __shared__ float Ws[HID * HID];
    __shared__ float bs[HID];
    if (threadIdx.x < HID * HID) Ws[threadIdx.x] = W2[threadIdx.x];
    if (threadIdx.x < HID)       bs[threadIdx.x] = b1[threadIdx.x];
    __syncthreads();

    int i = blockIdx.x * blockDim.x + threadIdx.x;
    if (i >= n) return;

    float d = g_dinv[i];
    float h[HID];
    float4* accp = (float4*)&g_acc[(size_t)i * HID];
#pragma unroll
    for (int q = 0; q < 4; q++) {
        float4 v = accp[q];
        h[4 * q + 0] = fmaxf(d * v.x + bs[4 * q + 0], 0.0f);
        h[4 * q + 1] = fmaxf(d * v.y + bs[4 * q + 1], 0.0f);
        h[4 * q + 2] = fmaxf(d * v.z + bs[4 * q + 2], 0.0f);
        h[4 * q + 3] = fmaxf(d * v.w + bs[4 * q + 3], 0.0f);
    }

    float t[HID];
#pragma unroll
    for (int j = 0; j < HID; j++) t[j] = 0.0f;
#pragma unroll
    for (int k = 0; k < HID; k++) {
        float hk = h[k];
#pragma unroll
        for (int j = 0; j < HID; j++) t[j] += hk * Ws[k * HID + j];
    }

    float4* hsp = (float4*)&g_hs[(size_t)i * HID];
#pragma unroll
    for (int q = 0; q < 4; q++) {
        float4 v;
        v.x = d * t[4 * q + 0];
        v.y = d * t[4 * q + 1];
        v.z = d * t[4 * q + 2];
        v.w = d * t[4 * q + 3];
        hsp[q]  = v;
        accp[q] = v;
    }
}

// h2 = relu(dinv*acc + b2);  out = h2 @ Wl + bl
__global__ void k_final(const float* __restrict__ b2, const float* __restrict__ Wl,
                        const float* __restrict__ bl, float* __restrict__ out, int n) {
    __shared__ float bs[HID];
    __shared__ float ws[HID];
    __shared__ float b0;
    if (threadIdx.x < HID) { bs[threadIdx.x] = b2[threadIdx.x]; ws[threadIdx.x] = Wl[threadIdx.x]; }
    if (threadIdx.x == 0)  b0 = bl[0];
    __syncthreads();

    int i = blockIdx.x * blockDim.x + threadIdx.x;
    if (i >= n) return;

    float d = g_dinv[i];
    float s = 0.0f;
    float4* accp = (float4*)&g_acc[(size_t)i * HID];
#pragma unroll
    for (int q = 0; q < 4; q++) {
        float4 v = accp[q];
        s += fmaxf(d * v.x + bs[4 * q + 0], 0.0f) * ws[4 * q + 0];
        s += fmaxf(d * v.y + bs[4 * q + 1], 0.0f) * ws[4 * q + 1];
        s += fmaxf(d * v.z + bs[4 * q + 2], 0.0f) * ws[4 * q + 2];
        s += fmaxf(d * v.w + bs[4 * q + 3], 0.0f) * ws[4 * q + 3];
    }
    out[i] = s + b0;
}

// ---------------- launch ----------------

extern "C" void kernel_launch(void* const* d_in, const int* in_sizes, int n_in,
                              void* d_out, int out_size) {
    const float* x   = (const float*)d_in[0];
    const int*   ei  = (const int*)  d_in[1];
    const float* W1  = (const float*)d_in[2];
    const float* b1  = (const float*)d_in[3];
    const float* W2  = (const float*)d_in[4];
    const float* b2  = (const float*)d_in[5];
    const float* Wl  = (const float*)d_in[6];
    const float* bl  = (const float*)d_in[7];
    float* out = (float*)d_out;

    const int n = in_sizes[0] / IN_CH;   // 100000
    const int e = in_sizes[1] / 2;       // 3200000
    const int* row = ei;
    const int* col = ei + e;

    const int TB = 256;
    const int gn = (n + TB - 1) / TB;
    const int ge = (e + TB - 1) / TB;

    k_init_deg<<<gn, TB>>>(n);
    k_count   <<<ge, TB>>>(col, e);
    k_dinv    <<<gn, TB>>>(n);

    // layer 1
    k_mm1     <<<gn, TB>>>(x, W1, n);
    k_scatter <<<ge, TB>>>(row, col, e);

    // layer 2 (fused relu+bias+matmul)
    k_mid     <<<gn, TB>>>(W2, b1, n);
    k_scatter <<<ge, TB>>>(row, col, e);

    // final linear (fused relu+bias+dot)
    k_final   <<<gn, TB>>>(b2, Wl, bl, out, n);
}

// round 3
// speedup vs baseline: 1.4904x; 1.4904x over previous
#include <cuda_runtime.h>
#include <cuda_bf16.h>

#define N_NODES 100000
#define N_EDGES 3200000
#define IN_CH   128
#define HID     16

#define SCAN_TB 1024
#define NBLK    ((N_NODES + SCAN_TB - 1) / SCAN_TB)   // 98

// ---------------- device scratch (no allocation allowed) ----------------
__device__ __align__(16) int   g_cnt [N_NODES];       // in-degree (edges only)
__device__ __align__(16) int   g_off [N_NODES];       // CSR offsets (exclusive scan)
__device__ __align__(16) int   g_offA[N_NODES];       // per-block exclusive scan
__device__ __align__(16) int   g_fill[N_NODES];       // fill cursors
__device__ __align__(16) int   g_bsum[NBLK];
__device__ __align__(16) int   g_bpre[NBLK];
__device__ __align__(16) int   g_adj [N_EDGES];       // CSR adjacency (source node per slot)
__device__ __align__(16) float g_dinv[N_NODES];
__device__ __align__(16) float g_hs  [N_NODES * HID]; // dinv-scaled features (message source)
__device__ __align__(16) float g_acc [N_NODES * HID]; // gathered sums

// ---------------- CSR build ----------------

__global__ void k_zero(int n) {
    int i = blockIdx.x * blockDim.x + threadIdx.x;
    if (i < n) g_cnt[i] = 0;
}

__global__ void k_count(const int* __restrict__ col, int e) {
    int i = blockIdx.x * blockDim.x + threadIdx.x;
    if (i < e) atomicAdd(&g_cnt[col[i]], 1);
}

// per-block exclusive scan (1024 elems/block) + block totals
__global__ void k_scanA(int n) {
    __shared__ int s[SCAN_TB];
    int i = blockIdx.x * SCAN_TB + threadIdx.x;
    int v = (i < n) ? g_cnt[i] : 0;
    s[threadIdx.x] = v;
    __syncthreads();
    for (int d = 1; d < SCAN_TB; d <<= 1) {
        int t = (threadIdx.x >= d) ? s[threadIdx.x - d] : 0;
        __syncthreads();
        s[threadIdx.x] += t;
        __syncthreads();
    }
    if (i < n) g_offA[i] = s[threadIdx.x] - v;   // exclusive
    if (threadIdx.x == SCAN_TB - 1) g_bsum[blockIdx.x] = s[SCAN_TB - 1];
}

// serial scan over NBLK (=98) block totals — trivial
__global__ void k_scanB(int nb) {
    if (threadIdx.x == 0 && blockIdx.x == 0) {
        int run = 0;
        for (int b = 0; b < nb; b++) { g_bpre[b] = run; run += g_bsum[b]; }
    }
}

// finalize offsets + cursors + dinv (deg = cnt + 1 self-loop)
__global__ void k_scanC(int n) {
    int i = blockIdx.x * blockDim.x + threadIdx.x;
    if (i >= n) return;
    int off = g_offA[i] + g_bpre[i / SCAN_TB];
    g_off[i]  = off;
    g_fill[i] = off;
    g_dinv[i] = rsqrtf((float)(g_cnt[i] + 1));
}

__global__ void k_fill(const int* __restrict__ row, const int* __restrict__ col, int e) {
    int i = blockIdx.x * blockDim.x + threadIdx.x;
    if (i >= e) return;
    int c = col[i];
    int pos = atomicAdd(&g_fill[c], 1);
    g_adj[pos] = row[i];
}

// ---------------- compute ----------------

// hs = dinv * (x @ W1)    (vectorized LDS.128 weight reads)
__global__ void k_mm1(const float* __restrict__ x, const float* __restrict__ W1, int n) {
    __shared__ float4 Ws[IN_CH * HID / 4];   // [k][q] row-major
    for (int t = threadIdx.x; t < IN_CH * HID / 4; t += blockDim.x)
        Ws[t] = ((const float4*)W1)[t];
    __syncthreads();

    int i = blockIdx.x * blockDim.x + threadIdx.x;
    if (i >= n) return;

    float a[HID];
#pragma unroll
    for (int j = 0; j < HID; j++) a[j] = 0.0f;

    const float4* xr = (const float4*)(x + (size_t)i * IN_CH);
#pragma unroll 8
    for (int k4 = 0; k4 < IN_CH / 4; k4++) {
        float4 xv = xr[k4];
        float xs[4] = {xv.x, xv.y, xv.z, xv.w};
#pragma unroll
        for (int r = 0; r < 4; r++) {
            const float4* w = &Ws[(k4 * 4 + r) * 4];
#pragma unroll
            for (int q = 0; q < 4; q++) {
                float4 wv = w[q];
                a[4 * q + 0] += xs[r] * wv.x;
                a[4 * q + 1] += xs[r] * wv.y;
                a[4 * q + 2] += xs[r] * wv.z;
                a[4 * q + 3] += xs[r] * wv.w;
            }
        }
    }

    float d = g_dinv[i];
    float4* hsp = (float4*)&g_hs[(size_t)i * HID];
#pragma unroll
    for (int q = 0; q < 4; q++) {
        float4 v;
        v.x = d * a[4 * q + 0];
        v.y = d * a[4 * q + 1];
        v.z = d * a[4 * q + 2];
        v.w = d * a[4 * q + 3];
        hsp[q] = v;
    }
}

// pull gather: acc[i] = hs[i] (self loop) + sum over incoming edges hs[adj[k]]
// 4 threads per node, one float4 lane each; 4-way unrolled for MLP.
__global__ void k_gather(int n) {
    int gid = blockIdx.x * blockDim.x + threadIdx.x;
    int i = gid >> 2;
    int q = gid & 3;
    if (i >= n) return;

    const float4* S = (const float4*)g_hs;
    float4 a = S[(size_t)i * 4 + q];   // self-loop term

    int k   = g_off[i];
    int end = k + g_cnt[i];

    for (; k + 3 < end; k += 4) {
        int r0 = __ldg(&g_adj[k + 0]);
        int r1 = __ldg(&g_adj[k + 1]);
        int r2 = __ldg(&g_adj[k + 2]);
        int r3 = __ldg(&g_adj[k + 3]);
        float4 v0 = S[(size_t)r0 * 4 + q];
        float4 v1 = S[(size_t)r1 * 4 + q];
        float4 v2 = S[(size_t)r2 * 4 + q];
        float4 v3 = S[(size_t)r3 * 4 + q];
        a.x += (v0.x + v1.x) + (v2.x + v3.x);
        a.y += (v0.y + v1.y) + (v2.y + v3.y);
        a.z += (v0.z + v1.z) + (v2.z + v3.z);
        a.w += (v0.w + v1.w) + (v2.w + v3.w);
    }
    for (; k < end; k++) {
        int r = __ldg(&g_adj[k]);
        float4 v = S[(size_t)r * 4 + q];
        a.x += v.x; a.y += v.y; a.z += v.z; a.w += v.w;
    }

    ((float4*)g_acc)[(size_t)i * 4 + q] = a;
}

// h1 = relu(dinv*acc + b1);  hs2 = dinv*(h1 @ W2)  -> g_hs
__global__ void k_mid(const float* __restrict__ W2, const float* __restrict__ b1, int n) {
    __shared__ float4 Ws[HID * HID / 4];
    __shared__ float  bs[HID];
    if (threadIdx.x < HID * HID / 4) Ws[threadIdx.x] = ((const float4*)W2)[threadIdx.x];
    if (threadIdx.x < HID)           bs[threadIdx.x] = b1[threadIdx.x];
    __syncthreads();

    int i = blockIdx.x * blockDim.x + threadIdx.x;
    if (i >= n) return;

    float d = g_dinv[i];
    float h[HID];
    const float4* accp = (const float4*)&g_acc[(size_t)i * HID];
#pragma unroll
    for (int q = 0; q < 4; q++) {
        float4 v = accp[q];
        h[4 * q + 0] = fmaxf(d * v.x + bs[4 * q + 0], 0.0f);
        h[4 * q + 1] = fmaxf(d * v.y + bs[4 * q + 1], 0.0f);
        h[4 * q + 2] = fmaxf(d * v.z + bs[4 * q + 2], 0.0f);
        h[4 * q + 3] = fmaxf(d * v.w + bs[4 * q + 3], 0.0f);
    }

    float t[HID];
#pragma unroll
    for (int j = 0; j < HID; j++) t[j] = 0.0f;
#pragma unroll
    for (int k = 0; k < HID; k++) {
        float hk = h[k];
#pragma unroll
        for (int q = 0; q < 4; q++) {
            float4 wv = Ws[k * 4 + q];
            t[4 * q + 0] += hk * wv.x;
            t[4 * q + 1] += hk * wv.y;
            t[4 * q + 2] += hk * wv.z;
            t[4 * q + 3] += hk * wv.w;
        }
    }

    float4* hsp = (float4*)&g_hs[(size_t)i * HID];
#pragma unroll
    for (int q = 0; q < 4; q++) {
        float4 v;
        v.x = d * t[4 * q + 0];
        v.y = d * t[4 * q + 1];
        v.z = d * t[4 * q + 2];
        v.w = d * t[4 * q + 3];
        hsp[q] = v;
    }
}

// h2 = relu(dinv*acc + b2);  out = h2 @ Wl + bl
__global__ void k_final(const float* __restrict__ b2, const float* __restrict__ Wl,
                        const float* __restrict__ bl, float* __restrict__ out, int n) {
    __shared__ float bs[HID];
    __shared__ float ws[HID];
    __shared__ float b0;
    if (threadIdx.x < HID) { bs[threadIdx.x] = b2[threadIdx.x]; ws[threadIdx.x] = Wl[threadIdx.x]; }
    if (threadIdx.x == 0)  b0 = bl[0];
    __syncthreads();

    int i = blockIdx.x * blockDim.x + threadIdx.x;
    if (i >= n) return;

    float d = g_dinv[i];
    float s = 0.0f;
    const float4* accp = (const float4*)&g_acc[(size_t)i * HID];
#pragma unroll
    for (int q = 0; q < 4; q++) {
        float4 v = accp[q];
        s += fmaxf(d * v.x + bs[4 * q + 0], 0.0f) * ws[4 * q + 0];
        s += fmaxf(d * v.y + bs[4 * q + 1], 0.0f) * ws[4 * q + 1];
        s += fmaxf(d * v.z + bs[4 * q + 2], 0.0f) * ws[4 * q + 2];
        s += fmaxf(d * v.w + bs[4 * q + 3], 0.0f) * ws[4 * q + 3];
    }
    out[i] = s + b0;
}

// ---------------- launch ----------------

extern "C" void kernel_launch(void* const* d_in, const int* in_sizes, int n_in,
                              void* d_out, int out_size) {
    const float* x   = (const float*)d_in[0];
    const int*   ei  = (const int*)  d_in[1];
    const float* W1  = (const float*)d_in[2];
    const float* b1  = (const float*)d_in[3];
    const float* W2  = (const float*)d_in[4];
    const float* b2  = (const float*)d_in[5];
    const float* Wl  = (const float*)d_in[6];
    const float* bl  = (const float*)d_in[7];
    float* out = (float*)d_out;

    const int n = in_sizes[0] / IN_CH;   // 100000
    const int e = in_sizes[1] / 2;       // 3200000
    const int* row = ei;
    const int* col = ei + e;

    const int TB = 256;
    const int gn = (n + TB - 1) / TB;
    const int ge = (e + TB - 1) / TB;
    const int gg = (n * 4 + TB - 1) / TB;
    const int nb = (n + SCAN_TB - 1) / SCAN_TB;

    // CSR build (per launch; graph-capturable, allocation-free)
    k_zero <<<gn, TB>>>(n);
    k_count<<<ge, TB>>>(col, e);
    k_scanA<<<nb, SCAN_TB>>>(n);
    k_scanB<<<1, 32>>>(nb);
    k_scanC<<<gn, TB>>>(n);
    k_fill <<<ge, TB>>>(row, col, e);

    // layer 1
    k_mm1   <<<gn, TB>>>(x, W1, n);
    k_gather<<<gg, TB>>>(n);

    // layer 2
    k_mid   <<<gn, TB>>>(W2, b1, n);
    k_gather<<<gg, TB>>>(n);

    // readout
    k_final <<<gn, TB>>>(b2, Wl, bl, out, n);
}

// round 4
// speedup vs baseline: 1.5844x; 1.0631x over previous
#include <cuda_runtime.h>
#include <cuda_bf16.h>

#define N_NODES 100000
#define N_EDGES 3200000
#define IN_CH   128
#define HID     16

#define SCAN_TB 1024
#define NBLK    ((N_NODES + SCAN_TB - 1) / SCAN_TB)   // 98

// ---------------- device scratch (no allocation allowed) ----------------
__device__ __align__(16) int   g_cnt [N_NODES];
__device__ __align__(16) int   g_off [N_NODES];
__device__ __align__(16) int   g_offA[N_NODES];
__device__ __align__(16) int   g_fill[N_NODES];
__device__ __align__(16) int   g_bsum[NBLK];
__device__ __align__(16) int   g_adj [N_EDGES];
__device__ __align__(16) float g_dinv[N_NODES];
__device__ __align__(16) float g_hs  [N_NODES * HID];  // layer-1 message source
__device__ __align__(16) float g_hs2 [N_NODES * HID];  // layer-2 message source

// ---------------- CSR build ----------------

__global__ void k_zero(int n) {
    int i = blockIdx.x * blockDim.x + threadIdx.x;
    if (i < n) g_cnt[i] = 0;
}

// 4 edges per thread, int4 loads
__global__ void k_count(const int* __restrict__ col, int e4) {
    int i = blockIdx.x * blockDim.x + threadIdx.x;
    if (i >= e4) return;
    int4 c = __ldg(&((const int4*)col)[i]);
    atomicAdd(&g_cnt[c.x], 1);
    atomicAdd(&g_cnt[c.y], 1);
    atomicAdd(&g_cnt[c.z], 1);
    atomicAdd(&g_cnt[c.w], 1);
}

// per-block (1024) exclusive scan + block totals
__global__ void k_scanA(int n) {
    __shared__ int s[SCAN_TB];
    int i = blockIdx.x * SCAN_TB + threadIdx.x;
    int v = (i < n) ? g_cnt[i] : 0;
    s[threadIdx.x] = v;
    __syncthreads();
    for (int d = 1; d < SCAN_TB; d <<= 1) {
        int t = (threadIdx.x >= d) ? s[threadIdx.x - d] : 0;
        __syncthreads();
        s[threadIdx.x] += t;
        __syncthreads();
    }
    if (i < n) g_offA[i] = s[threadIdx.x] - v;
    if (threadIdx.x == SCAN_TB - 1) g_bsum[blockIdx.x] = s[SCAN_TB - 1];
}

// finalize offsets + cursors + dinv; block prefix of g_bsum computed in-block
__global__ void k_scanC(int n, int nb) {
    __shared__ int s_pre;
    if (threadIdx.x < 32) {
        int sb = (blockIdx.x * (int)blockDim.x) / SCAN_TB;   // block totals strictly before
        int sum = 0;
        for (int t = threadIdx.x; t < sb; t += 32) sum += g_bsum[t];
#pragma unroll
        for (int o = 16; o; o >>= 1) sum += __shfl_xor_sync(0xffffffffu, sum, o);
        if (threadIdx.x == 0) s_pre = sum;
    }
    __syncthreads();

    int i = blockIdx.x * blockDim.x + threadIdx.x;
    if (i >= n) return;
    int off = g_offA[i] + s_pre;
    g_off[i]  = off;
    g_fill[i] = off;
    g_dinv[i] = rsqrtf((float)(g_cnt[i] + 1));
}

// 4 edges per thread, int4 loads
__global__ void k_fill(const int* __restrict__ row, const int* __restrict__ col, int e4) {
    int i = blockIdx.x * blockDim.x + threadIdx.x;
    if (i >= e4) return;
    int4 r = __ldg(&((const int4*)row)[i]);
    int4 c = __ldg(&((const int4*)col)[i]);
    g_adj[atomicAdd(&g_fill[c.x], 1)] = r.x;
    g_adj[atomicAdd(&g_fill[c.y], 1)] = r.y;
    g_adj[atomicAdd(&g_fill[c.z], 1)] = r.z;
    g_adj[atomicAdd(&g_fill[c.w], 1)] = r.w;
}

// ---------------- compute ----------------

// hs = dinv * (x @ W1)
__global__ void k_mm1(const float* __restrict__ x, const float* __restrict__ W1, int n) {
    __shared__ float4 Ws[IN_CH * HID / 4];
    for (int t = threadIdx.x; t < IN_CH * HID / 4; t += blockDim.x)
        Ws[t] = ((const float4*)W1)[t];
    __syncthreads();

    int i = blockIdx.x * blockDim.x + threadIdx.x;
    if (i >= n) return;

    float a[HID];
#pragma unroll
    for (int j = 0; j < HID; j++) a[j] = 0.0f;

    const float4* xr = (const float4*)(x + (size_t)i * IN_CH);
#pragma unroll 8
    for (int k4 = 0; k4 < IN_CH / 4; k4++) {
        float4 xv = xr[k4];
        float xs[4] = {xv.x, xv.y, xv.z, xv.w};
#pragma unroll
        for (int r = 0; r < 4; r++) {
            const float4* w = &Ws[(k4 * 4 + r) * 4];
#pragma unroll
            for (int q = 0; q < 4; q++) {
                float4 wv = w[q];
                a[4 * q + 0] += xs[r] * wv.x;
                a[4 * q + 1] += xs[r] * wv.y;
                a[4 * q + 2] += xs[r] * wv.z;
                a[4 * q + 3] += xs[r] * wv.w;
            }
        }
    }

    float d = g_dinv[i];
    float4* hsp = (float4*)&g_hs[(size_t)i * HID];
#pragma unroll
    for (int q = 0; q < 4; q++) {
        float4 v;
        v.x = d * a[4 * q + 0];
        v.y = d * a[4 * q + 1];
        v.z = d * a[4 * q + 2];
        v.w = d * a[4 * q + 3];
        hsp[q] = v;
    }
}

// quad accumulate helper: a += hs[adj[k..end)] lane-q float4, 8-way unrolled MLP
__device__ __forceinline__ float4 quad_gather(const float4* __restrict__ S,
                                              float4 a, int k, int end, int q) {
    for (; k + 8 <= end; k += 8) {
        int r[8];
#pragma unroll
        for (int u = 0; u < 8; u++) r[u] = __ldg(&g_adj[k + u]);
        float4 v[8];
#pragma unroll
        for (int u = 0; u < 8; u++) v[u] = S[(size_t)r[u] * 4 + q];
#pragma unroll
        for (int u = 0; u < 8; u++) {
            a.x += v[u].x; a.y += v[u].y; a.z += v[u].z; a.w += v[u].w;
        }
    }
    for (; k < end; k++) {
        int r = __ldg(&g_adj[k]);
        float4 v = S[(size_t)r * 4 + q];
        a.x += v.x; a.y += v.y; a.z += v.z; a.w += v.w;
    }
    return a;
}

// gather layer-1 messages + fused: h1 = relu(d*a + b1); hs2 = d*(h1 @ W2)
__global__ void k_gather_mid(const float* __restrict__ W2, const float* __restrict__ b1, int n) {
    __shared__ float4 Ws[HID * HID / 4];   // W2 row-major as float4 per (k, qcol)
    if (threadIdx.x < HID * HID / 4) Ws[threadIdx.x] = ((const float4*)W2)[threadIdx.x];
    __syncthreads();

    int gid = blockIdx.x * blockDim.x + threadIdx.x;
    int i = gid >> 2;
    int q = gid & 3;
    if (i >= n) return;

    const float4* S = (const float4*)g_hs;
    float4 a = S[(size_t)i * 4 + q];                       // self-loop seed
    int off = g_off[i];
    a = quad_gather(S, a, off, off + g_cnt[i], q);

    float d = g_dinv[i];
    float4 bq = __ldg(&((const float4*)b1)[q]);
    float hq[4];
    hq[0] = fmaxf(d * a.x + bq.x, 0.0f);
    hq[1] = fmaxf(d * a.y + bq.y, 0.0f);
    hq[2] = fmaxf(d * a.z + bq.z, 0.0f);
    hq[3] = fmaxf(d * a.w + bq.w, 0.0f);

    // exchange full h[16] within the quad
    unsigned lane = threadIdx.x & 31u;
    unsigned qmask = 0xFu << (lane & ~3u);
    float h[HID];
#pragma unroll
    for (int p = 0; p < 4; p++) {
#pragma unroll
        for (int j = 0; j < 4; j++)
            h[p * 4 + j] = __shfl_sync(qmask, hq[j], p, 4);
    }

    // t[4q+j] = sum_k h[k] * W2[k][4q+j]
    float4 t = make_float4(0.f, 0.f, 0.f, 0.f);
#pragma unroll
    for (int k = 0; k < HID; k++) {
        float4 wv = Ws[k * 4 + q];
        t.x += h[k] * wv.x;
        t.y += h[k] * wv.y;
        t.z += h[k] * wv.z;
        t.w += h[k] * wv.w;
    }

    float4 o;
    o.x = d * t.x; o.y = d * t.y; o.z = d * t.z; o.w = d * t.w;
    ((float4*)g_hs2)[(size_t)i * 4 + q] = o;
}

// gather layer-2 messages + fused readout: out = relu(d*a + b2) . Wl + bl
__global__ void k_gather_final(const float* __restrict__ b2, const float* __restrict__ Wl,
                               const float* __restrict__ bl, float* __restrict__ out, int n) {
    int gid = blockIdx.x * blockDim.x + threadIdx.x;
    int i = gid >> 2;
    int q = gid & 3;
    if (i >= n) return;

    const float4* S = (const float4*)g_hs2;
    float4 a = S[(size_t)i * 4 + q];
    int off = g_off[i];
    a = quad_gather(S, a, off, off + g_cnt[i], q);

    float d = g_dinv[i];
    float4 bq = __ldg(&((const float4*)b2)[q]);
    float4 wq = __ldg(&((const float4*)Wl)[q]);
    float s = fmaxf(d * a.x + bq.x, 0.0f) * wq.x
            + fmaxf(d * a.y + bq.y, 0.0f) * wq.y
            + fmaxf(d * a.z + bq.z, 0.0f) * wq.z
            + fmaxf(d * a.w + bq.w, 0.0f) * wq.w;

    unsigned lane = threadIdx.x & 31u;
    unsigned qmask = 0xFu << (lane & ~3u);
    s += __shfl_xor_sync(qmask, s, 1, 4);
    s += __shfl_xor_sync(qmask, s, 2, 4);
    if (q == 0) out[i] = s + __ldg(bl);
}

// ---------------- launch ----------------

extern "C" void kernel_launch(void* const* d_in, const int* in_sizes, int n_in,
                              void* d_out, int out_size) {
    const float* x   = (const float*)d_in[0];
    const int*   ei  = (const int*)  d_in[1];
    const float* W1  = (const float*)d_in[2];
    const float* b1  = (const float*)d_in[3];
    const float* W2  = (const float*)d_in[4];
    const float* b2  = (const float*)d_in[5];
    const float* Wl  = (const float*)d_in[6];
    const float* bl  = (const float*)d_in[7];
    float* out = (float*)d_out;

    const int n = in_sizes[0] / IN_CH;   // 100000
    const int e = in_sizes[1] / 2;       // 3200000 (multiple of 4)
    const int* row = ei;
    const int* col = ei + e;

    const int TB  = 256;
    const int gn  = (n + TB - 1) / TB;
    const int e4  = e / 4;
    const int ge4 = (e4 + TB - 1) / TB;
    const int gg  = (n * 4 + TB - 1) / TB;
    const int nb  = (n + SCAN_TB - 1) / SCAN_TB;

    // CSR build
    k_zero <<<gn,  TB>>>(n);
    k_count<<<ge4, TB>>>(col, e4);
    k_scanA<<<nb,  SCAN_TB>>>(n);
    k_scanC<<<gn,  TB>>>(n, nb);
    k_fill <<<ge4, TB>>>(row, col, e4);

    // layer 1 (+ fused layer-2 transform)
    k_mm1       <<<gn, TB>>>(x, W1, n);
    k_gather_mid<<<gg, TB>>>(W2, b1, n);

    // layer 2 (+ fused readout)
    k_gather_final<<<gg, TB>>>(b2, Wl, bl, out, n);
}

// round 5
// speedup vs baseline: 1.6267x; 1.0267x over previous
#include <cuda_runtime.h>
#include <cuda_bf16.h>

#define N_NODES 100000
#define N_EDGES 3200000
#define IN_CH   128
#define HID     16

#define SCAN_TB 1024
#define NBLK    ((N_NODES + SCAN_TB - 1) / SCAN_TB)   // 98

// ---------------- device scratch (no allocation allowed) ----------------
__device__ __align__(16) int   g_cnt [N_NODES];
__device__ __align__(16) int   g_off [N_NODES];
__device__ __align__(16) int   g_offA[N_NODES];
__device__ __align__(16) int   g_fill[N_NODES];
__device__ __align__(16) int   g_bsum[NBLK];
__device__ __align__(16) int   g_bpre[NBLK];
__device__ int                 g_done;
__device__ __align__(16) int   g_adj [N_EDGES];
__device__ __align__(16) float g_dinv[N_NODES];
__device__ __align__(16) float g_hs  [N_NODES * HID];  // layer-1 message source
__device__ __align__(16) float g_hs2 [N_NODES * HID];  // layer-2 message source

// ---------------- CSR build ----------------

__global__ void k_zero(int n4) {
    int i = blockIdx.x * blockDim.x + threadIdx.x;
    if (i < n4) ((int4*)g_cnt)[i] = make_int4(0, 0, 0, 0);
    if (i == 0) g_done = 0;
}

// 4 edges per thread, int4 loads
__global__ void k_count(const int* __restrict__ col, int e4) {
    int i = blockIdx.x * blockDim.x + threadIdx.x;
    if (i >= e4) return;
    int4 c = __ldg(&((const int4*)col)[i]);
    atomicAdd(&g_cnt[c.x], 1);
    atomicAdd(&g_cnt[c.y], 1);
    atomicAdd(&g_cnt[c.z], 1);
    atomicAdd(&g_cnt[c.w], 1);
}

// per-block (1024) exclusive scan + block totals; last-arriving block scans the totals
__global__ void k_scanA(int n, int nb) {
    __shared__ int s[SCAN_TB];
    __shared__ int is_last;
    int i = blockIdx.x * SCAN_TB + threadIdx.x;
    int v = (i < n) ? g_cnt[i] : 0;
    s[threadIdx.x] = v;
    __syncthreads();
    for (int d = 1; d < SCAN_TB; d <<= 1) {
        int t = (threadIdx.x >= d) ? s[threadIdx.x - d] : 0;
        __syncthreads();
        s[threadIdx.x] += t;
        __syncthreads();
    }
    if (i < n) g_offA[i] = s[threadIdx.x] - v;
    if (threadIdx.x == SCAN_TB - 1) g_bsum[blockIdx.x] = s[SCAN_TB - 1];

    __threadfence();
    if (threadIdx.x == 0) is_last = (atomicAdd(&g_done, 1) == nb - 1);
    __syncthreads();
    if (!is_last) return;

    __threadfence();   // acquire all blocks' g_bsum writes
    int b = threadIdx.x;
    int bv = (b < nb) ? g_bsum[b] : 0;
    s[b] = bv;
    __syncthreads();
    for (int d = 1; d < SCAN_TB; d <<= 1) {
        int t = (b >= d) ? s[b - d] : 0;
        __syncthreads();
        s[b] += t;
        __syncthreads();
    }
    if (b < nb) g_bpre[b] = s[b] - bv;   // exclusive
}

// finalize offsets + cursors + dinv (pure elementwise)
__global__ void k_scanC(int n) {
    int i = blockIdx.x * blockDim.x + threadIdx.x;
    if (i >= n) return;
    int off = g_offA[i] + g_bpre[i >> 10];
    g_off[i]  = off;
    g_fill[i] = off;
    g_dinv[i] = rsqrtf((float)(g_cnt[i] + 1));
}

// 4 edges per thread, int4 loads
__global__ void k_fill(const int* __restrict__ row, const int* __restrict__ col, int e4) {
    int i = blockIdx.x * blockDim.x + threadIdx.x;
    if (i >= e4) return;
    int4 r = __ldg(&((const int4*)row)[i]);
    int4 c = __ldg(&((const int4*)col)[i]);
    g_adj[atomicAdd(&g_fill[c.x], 1)] = r.x;
    g_adj[atomicAdd(&g_fill[c.y], 1)] = r.y;
    g_adj[atomicAdd(&g_fill[c.z], 1)] = r.z;
    g_adj[atomicAdd(&g_fill[c.w], 1)] = r.w;
}

// ---------------- compute ----------------

// hs = dinv * (x @ W1)
__global__ void k_mm1(const float* __restrict__ x, const float* __restrict__ W1, int n) {
    __shared__ float4 Ws[IN_CH * HID / 4];
    for (int t = threadIdx.x; t < IN_CH * HID / 4; t += blockDim.x)
        Ws[t] = ((const float4*)W1)[t];
    __syncthreads();

    int i = blockIdx.x * blockDim.x + threadIdx.x;
    if (i >= n) return;

    float a[HID];
#pragma unroll
    for (int j = 0; j < HID; j++) a[j] = 0.0f;

    const float4* xr = (const float4*)(x + (size_t)i * IN_CH);
#pragma unroll 8
    for (int k4 = 0; k4 < IN_CH / 4; k4++) {
        float4 xv = xr[k4];
        float xs[4] = {xv.x, xv.y, xv.z, xv.w};
#pragma unroll
        for (int r = 0; r < 4; r++) {
            const float4* w = &Ws[(k4 * 4 + r) * 4];
#pragma unroll
            for (int q = 0; q < 4; q++) {
                float4 wv = w[q];
                a[4 * q + 0] += xs[r] * wv.x;
                a[4 * q + 1] += xs[r] * wv.y;
                a[4 * q + 2] += xs[r] * wv.z;
                a[4 * q + 3] += xs[r] * wv.w;
            }
        }
    }

    float d = g_dinv[i];
    float4* hsp = (float4*)&g_hs[(size_t)i * HID];
#pragma unroll
    for (int q = 0; q < 4; q++) {
        float4 v;
        v.x = d * a[4 * q + 0];
        v.y = d * a[4 * q + 1];
        v.z = d * a[4 * q + 2];
        v.w = d * a[4 * q + 3];
        hsp[q] = v;
    }
}

// quad accumulate with software-pipelined adjacency prefetch
__device__ __forceinline__ float4 quad_gather(const float4* __restrict__ S,
                                              float4 a, int k, int end, int q) {
    if (k + 8 <= end) {
        int r[8];
#pragma unroll
        for (int u = 0; u < 8; u++) r[u] = __ldg(&g_adj[k + u]);
        k += 8;
        while (k + 8 <= end) {
            int rn[8];
#pragma unroll
            for (int u = 0; u < 8; u++) rn[u] = __ldg(&g_adj[k + u]);   // prefetch next
            float4 v[8];
#pragma unroll
            for (int u = 0; u < 8; u++) v[u] = S[(size_t)r[u] * 4 + q];
#pragma unroll
            for (int u = 0; u < 8; u++) {
                a.x += v[u].x; a.y += v[u].y; a.z += v[u].z; a.w += v[u].w;
            }
#pragma unroll
            for (int u = 0; u < 8; u++) r[u] = rn[u];
            k += 8;
        }
        float4 v[8];
#pragma unroll
        for (int u = 0; u < 8; u++) v[u] = S[(size_t)r[u] * 4 + q];
#pragma unroll
        for (int u = 0; u < 8; u++) {
            a.x += v[u].x; a.y += v[u].y; a.z += v[u].z; a.w += v[u].w;
        }
    }
    for (; k < end; k++) {
        int r = __ldg(&g_adj[k]);
        float4 v = S[(size_t)r * 4 + q];
        a.x += v.x; a.y += v.y; a.z += v.z; a.w += v.w;
    }
    return a;
}

// gather layer-1 messages + fused: h1 = relu(d*a + b1); hs2 = d*(h1 @ W2)
__global__ void k_gather_mid(const float* __restrict__ W2, const float* __restrict__ b1, int n) {
    __shared__ float4 Ws[HID * HID / 4];
    if (threadIdx.x < HID * HID / 4) Ws[threadIdx.x] = ((const float4*)W2)[threadIdx.x];
    __syncthreads();

    int gid = blockIdx.x * blockDim.x + threadIdx.x;
    int i = gid >> 2;
    int q = gid & 3;
    if (i >= n) return;

    const float4* S = (const float4*)g_hs;
    float4 a = S[(size_t)i * 4 + q];                       // self-loop seed
    int off = g_off[i];
    a = quad_gather(S, a, off, off + g_cnt[i], q);

    float d = g_dinv[i];
    float4 bq = __ldg(&((const float4*)b1)[q]);
    float hq[4];
    hq[0] = fmaxf(d * a.x + bq.x, 0.0f);
    hq[1] = fmaxf(d * a.y + bq.y, 0.0f);
    hq[2] = fmaxf(d * a.z + bq.z, 0.0f);
    hq[3] = fmaxf(d * a.w + bq.w, 0.0f);

    unsigned lane = threadIdx.x & 31u;
    unsigned qmask = 0xFu << (lane & ~3u);
    float h[HID];
#pragma unroll
    for (int p = 0; p < 4; p++) {
#pragma unroll
        for (int j = 0; j < 4; j++)
            h[p * 4 + j] = __shfl_sync(qmask, hq[j], p, 4);
    }

    float4 t = make_float4(0.f, 0.f, 0.f, 0.f);
#pragma unroll
    for (int k = 0; k < HID; k++) {
        float4 wv = Ws[k * 4 + q];
        t.x += h[k] * wv.x;
        t.y += h[k] * wv.y;
        t.z += h[k] * wv.z;
        t.w += h[k] * wv.w;
    }

    float4 o;
    o.x = d * t.x; o.y = d * t.y; o.z = d * t.z; o.w = d * t.w;
    ((float4*)g_hs2)[(size_t)i * 4 + q] = o;
}

// gather layer-2 messages + fused readout: out = relu(d*a + b2) . Wl + bl
__global__ void k_gather_final(const float* __restrict__ b2, const float* __restrict__ Wl,
                               const float* __restrict__ bl, float* __restrict__ out, int n) {
    int gid = blockIdx.x * blockDim.x + threadIdx.x;
    int i = gid >> 2;
    int q = gid & 3;
    if (i >= n) return;

    const float4* S = (const float4*)g_hs2;
    float4 a = S[(size_t)i * 4 + q];
    int off = g_off[i];
    a = quad_gather(S, a, off, off + g_cnt[i], q);

    float d = g_dinv[i];
    float4 bq = __ldg(&((const float4*)b2)[q]);
    float4 wq = __ldg(&((const float4*)Wl)[q]);
    float s = fmaxf(d * a.x + bq.x, 0.0f) * wq.x
            + fmaxf(d * a.y + bq.y, 0.0f) * wq.y
            + fmaxf(d * a.z + bq.z, 0.0f) * wq.z
            + fmaxf(d * a.w + bq.w, 0.0f) * wq.w;

    unsigned lane = threadIdx.x & 31u;
    unsigned qmask = 0xFu << (lane & ~3u);
    s += __shfl_xor_sync(qmask, s, 1, 4);
    s += __shfl_xor_sync(qmask, s, 2, 4);
    if (q == 0) out[i] = s + __ldg(bl);
}

// ---------------- launch ----------------

extern "C" void kernel_launch(void* const* d_in, const int* in_sizes, int n_in,
                              void* d_out, int out_size) {
    const float* x   = (const float*)d_in[0];
    const int*   ei  = (const int*)  d_in[1];
    const float* W1  = (const float*)d_in[2];
    const float* b1  = (const float*)d_in[3];
    const float* W2  = (const float*)d_in[4];
    const float* b2  = (const float*)d_in[5];
    const float* Wl  = (const float*)d_in[6];
    const float* bl  = (const float*)d_in[7];
    float* out = (float*)d_out;

    const int n = in_sizes[0] / IN_CH;   // 100000
    const int e = in_sizes[1] / 2;       // 3200000 (multiple of 4)
    const int* row = ei;
    const int* col = ei + e;

    const int TB  = 256;
    const int gn  = (n + TB - 1) / TB;
    const int n4  = n / 4;               // 25000 exact
    const int e4  = e / 4;
    const int ge4 = (e4 + TB - 1) / TB;
    const int gg  = (n * 4 + TB - 1) / TB;
    const int nb  = (n + SCAN_TB - 1) / SCAN_TB;

    // CSR build
    k_zero <<<(n4 + TB - 1) / TB, TB>>>(n4);
    k_count<<<ge4, TB>>>(col, e4);
    k_scanA<<<nb,  SCAN_TB>>>(n, nb);
    k_scanC<<<gn,  TB>>>(n);
    k_fill <<<ge4, TB>>>(row, col, e4);

    // layer 1 (+ fused layer-2 transform)
    k_mm1       <<<gn, TB>>>(x, W1, n);
    k_gather_mid<<<gg, TB>>>(W2, b1, n);

    // layer 2 (+ fused readout)
    k_gather_final<<<gg, TB>>>(b2, Wl, bl, out, n);
}

// round 6
// speedup vs baseline: 1.6556x; 1.0178x over previous
#include <cuda_runtime.h>
#include <cuda_fp16.h>
#include <cuda_bf16.h>

#define N_NODES 100000
#define N_EDGES 3200000
#define IN_CH   128
#define HID     16

#define SCAN_TB 1024
#define NBLK    ((N_NODES + SCAN_TB - 1) / SCAN_TB)   // 98

// ---------------- device scratch (no allocation allowed) ----------------
__device__ __align__(16) int    g_cnt [N_NODES];
__device__ __align__(16) int    g_off [N_NODES];
__device__ __align__(16) int    g_offA[N_NODES];
__device__ __align__(16) int    g_fill[N_NODES];
__device__ __align__(16) int    g_bsum[NBLK];
__device__ __align__(16) int    g_bpre[NBLK];
__device__ int                  g_done;
__device__ __align__(16) int    g_adj [N_EDGES];
__device__ __align__(16) float  g_dinv[N_NODES];
__device__ __align__(16) __half g_hs  [N_NODES * HID];  // layer-1 messages (fp16)
__device__ __align__(16) __half g_hs2 [N_NODES * HID];  // layer-2 messages (fp16)

// ---------------- CSR build ----------------

__global__ void k_zero(int n4) {
    int i = blockIdx.x * blockDim.x + threadIdx.x;
    if (i < n4) ((int4*)g_cnt)[i] = make_int4(0, 0, 0, 0);
    if (i == 0) g_done = 0;
}

__global__ void k_count(const int* __restrict__ col, int e4) {
    int i = blockIdx.x * blockDim.x + threadIdx.x;
    if (i >= e4) return;
    int4 c = __ldg(&((const int4*)col)[i]);
    atomicAdd(&g_cnt[c.x], 1);
    atomicAdd(&g_cnt[c.y], 1);
    atomicAdd(&g_cnt[c.z], 1);
    atomicAdd(&g_cnt[c.w], 1);
}

// per-block exclusive scan + block totals; last-arriving block scans the totals
__global__ void k_scanA(int n, int nb) {
    __shared__ int s[SCAN_TB];
    __shared__ int is_last;
    int i = blockIdx.x * SCAN_TB + threadIdx.x;
    int v = (i < n) ? g_cnt[i] : 0;
    s[threadIdx.x] = v;
    __syncthreads();
    for (int d = 1; d < SCAN_TB; d <<= 1) {
        int t = (threadIdx.x >= d) ? s[threadIdx.x - d] : 0;
        __syncthreads();
        s[threadIdx.x] += t;
        __syncthreads();
    }
    if (i < n) g_offA[i] = s[threadIdx.x] - v;
    if (threadIdx.x == SCAN_TB - 1) g_bsum[blockIdx.x] = s[SCAN_TB - 1];

    __threadfence();
    if (threadIdx.x == 0) is_last = (atomicAdd(&g_done, 1) == nb - 1);
    __syncthreads();
    if (!is_last) return;

    __threadfence();
    int b = threadIdx.x;
    int bv = (b < nb) ? g_bsum[b] : 0;
    s[b] = bv;
    __syncthreads();
    for (int d = 1; d < SCAN_TB; d <<= 1) {
        int t = (b >= d) ? s[b - d] : 0;
        __syncthreads();
        s[b] += t;
        __syncthreads();
    }
    if (b < nb) g_bpre[b] = s[b] - bv;
}

__global__ void k_scanC(int n) {
    int i = blockIdx.x * blockDim.x + threadIdx.x;
    if (i >= n) return;
    int off = g_offA[i] + g_bpre[i >> 10];
    g_off[i]  = off;
    g_fill[i] = off;
    g_dinv[i] = rsqrtf((float)(g_cnt[i] + 1));
}

__global__ void k_fill(const int* __restrict__ row, const int* __restrict__ col, int e4) {
    int i = blockIdx.x * blockDim.x + threadIdx.x;
    if (i >= e4) return;
    int4 r = __ldg(&((const int4*)row)[i]);
    int4 c = __ldg(&((const int4*)col)[i]);
    g_adj[atomicAdd(&g_fill[c.x], 1)] = r.x;
    g_adj[atomicAdd(&g_fill[c.y], 1)] = r.y;
    g_adj[atomicAdd(&g_fill[c.z], 1)] = r.z;
    g_adj[atomicAdd(&g_fill[c.w], 1)] = r.w;
}

// ---------------- compute ----------------

// hs = fp16( dinv * (x @ W1) )
__global__ void k_mm1(const float* __restrict__ x, const float* __restrict__ W1, int n) {
    __shared__ float4 Ws[IN_CH * HID / 4];
    for (int t = threadIdx.x; t < IN_CH * HID / 4; t += blockDim.x)
        Ws[t] = ((const float4*)W1)[t];
    __syncthreads();

    int i = blockIdx.x * blockDim.x + threadIdx.x;
    if (i >= n) return;

    float a[HID];
#pragma unroll
    for (int j = 0; j < HID; j++) a[j] = 0.0f;

    const float4* xr = (const float4*)(x + (size_t)i * IN_CH);
#pragma unroll 8
    for (int k4 = 0; k4 < IN_CH / 4; k4++) {
        float4 xv = xr[k4];
        float xs[4] = {xv.x, xv.y, xv.z, xv.w};
#pragma unroll
        for (int r = 0; r < 4; r++) {
            const float4* w = &Ws[(k4 * 4 + r) * 4];
#pragma unroll
            for (int q = 0; q < 4; q++) {
                float4 wv = w[q];
                a[4 * q + 0] += xs[r] * wv.x;
                a[4 * q + 1] += xs[r] * wv.y;
                a[4 * q + 2] += xs[r] * wv.z;
                a[4 * q + 3] += xs[r] * wv.w;
            }
        }
    }

    float d = g_dinv[i];
    uint4 pack[2];
    __half2* hp = (__half2*)pack;
#pragma unroll
    for (int j = 0; j < 8; j++)
        hp[j] = __floats2half2_rn(d * a[2 * j], d * a[2 * j + 1]);
    ((uint4*)g_hs)[(size_t)i * 2 + 0] = pack[0];
    ((uint4*)g_hs)[(size_t)i * 2 + 1] = pack[1];
}

// accumulate one fp16x8 message into fp32 acc[8]
__device__ __forceinline__ void acc_msg(float* a, uint4 v) {
    const __half2* h = reinterpret_cast<const __half2*>(&v);
#pragma unroll
    for (int t = 0; t < 4; t++) {
        float2 f = __half22float2(h[t]);
        a[2 * t]     += f.x;
        a[2 * t + 1] += f.y;
    }
}

// pair gather: 2 lanes/node, lane p owns features [8p, 8p+8); pipelined adj prefetch
__device__ __forceinline__ void pair_gather(const uint4* __restrict__ S,
                                            float* a, int k, int end, int p) {
    if (k + 8 <= end) {
        int r[8];
#pragma unroll
        for (int u = 0; u < 8; u++) r[u] = __ldg(&g_adj[k + u]);
        k += 8;
        while (k + 8 <= end) {
            int rn[8];
#pragma unroll
            for (int u = 0; u < 8; u++) rn[u] = __ldg(&g_adj[k + u]);
            uint4 v[8];
#pragma unroll
            for (int u = 0; u < 8; u++) v[u] = S[(size_t)r[u] * 2 + p];
#pragma unroll
            for (int u = 0; u < 8; u++) acc_msg(a, v[u]);
#pragma unroll
            for (int u = 0; u < 8; u++) r[u] = rn[u];
            k += 8;
        }
        uint4 v[8];
#pragma unroll
        for (int u = 0; u < 8; u++) v[u] = S[(size_t)r[u] * 2 + p];
#pragma unroll
        for (int u = 0; u < 8; u++) acc_msg(a, v[u]);
    }
    for (; k < end; k++) {
        uint4 v = S[(size_t)__ldg(&g_adj[k]) * 2 + p];
        acc_msg(a, v);
    }
}

// gather layer-1 + fused: h1 = relu(d*a + b1); hs2 = fp16(d*(h1 @ W2))
__global__ void k_gather_mid(const float* __restrict__ W2, const float* __restrict__ b1, int n) {
    __shared__ float Ws[HID * HID];
    if (threadIdx.x < HID * HID / 4)
        ((float4*)Ws)[threadIdx.x] = ((const float4*)W2)[threadIdx.x];
    __syncthreads();

    int gid = blockIdx.x * blockDim.x + threadIdx.x;
    int i = gid >> 1;
    int p = gid & 1;
    if (i >= n) return;

    const uint4* S = (const uint4*)g_hs;
    float a[8];
#pragma unroll
    for (int j = 0; j < 8; j++) a[j] = 0.0f;
    acc_msg(a, S[(size_t)i * 2 + p]);                  // self-loop seed
    int off = g_off[i];
    pair_gather(S, a, off, off + g_cnt[i], p);

    float d = g_dinv[i];
    float h8[8];
    const float* bb = b1 + p * 8;
#pragma unroll
    for (int j = 0; j < 8; j++)
        h8[j] = fmaxf(d * a[j] + __ldg(&bb[j]), 0.0f);

    unsigned lane = threadIdx.x & 31u;
    unsigned pm = 0x3u << (lane & ~1u);
    float hall[HID];
#pragma unroll
    for (int j = 0; j < 8; j++) hall[p * 8 + j] = h8[j];
#pragma unroll
    for (int j = 0; j < 8; j++)
        hall[(p ^ 1) * 8 + j] = __shfl_xor_sync(pm, h8[j], 1, 2);

    float t[8];
#pragma unroll
    for (int j = 0; j < 8; j++) t[j] = 0.0f;
#pragma unroll
    for (int k = 0; k < HID; k++) {
        float hk = hall[k];
        const float* w = &Ws[k * HID + p * 8];
#pragma unroll
        for (int j = 0; j < 8; j++) t[j] += hk * w[j];
    }

    uint4 pack;
    __half2* hp = (__half2*)&pack;
#pragma unroll
    for (int j = 0; j < 4; j++)
        hp[j] = __floats2half2_rn(d * t[2 * j], d * t[2 * j + 1]);
    ((uint4*)g_hs2)[(size_t)i * 2 + p] = pack;
}

// gather layer-2 + fused readout: out = relu(d*a + b2) . Wl + bl
__global__ void k_gather_final(const float* __restrict__ b2, const float* __restrict__ Wl,
                               const float* __restrict__ bl, float* __restrict__ out, int n) {
    int gid = blockIdx.x * blockDim.x + threadIdx.x;
    int i = gid >> 1;
    int p = gid & 1;
    if (i >= n) return;

    const uint4* S = (const uint4*)g_hs2;
    float a[8];
#pragma unroll
    for (int j = 0; j < 8; j++) a[j] = 0.0f;
    acc_msg(a, S[(size_t)i * 2 + p]);
    int off = g_off[i];
    pair_gather(S, a, off, off + g_cnt[i], p);

    float d = g_dinv[i];
    const float* bb = b2 + p * 8;
    const float* ww = Wl + p * 8;
    float s = 0.0f;
#pragma unroll
    for (int j = 0; j < 8; j++)
        s += fmaxf(d * a[j] + __ldg(&bb[j]), 0.0f) * __ldg(&ww[j]);

    unsigned lane = threadIdx.x & 31u;
    unsigned pm = 0x3u << (lane & ~1u);
    s += __shfl_xor_sync(pm, s, 1, 2);
    if (p == 0) out[i] = s + __ldg(bl);
}

// ---------------- launch ----------------

extern "C" void kernel_launch(void* const* d_in, const int* in_sizes, int n_in,
                              void* d_out, int out_size) {
    const float* x   = (const float*)d_in[0];
    const int*   ei  = (const int*)  d_in[1];
    const float* W1  = (const float*)d_in[2];
    const float* b1  = (const float*)d_in[3];
    const float* W2  = (const float*)d_in[4];
    const float* b2  = (const float*)d_in[5];
    const float* Wl  = (const float*)d_in[6];
    const float* bl  = (const float*)d_in[7];
    float* out = (float*)d_out;

    const int n = in_sizes[0] / IN_CH;   // 100000
    const int e = in_sizes[1] / 2;       // 3200000
    const int* row = ei;
    const int* col = ei + e;

    const int TB  = 256;
    const int gn  = (n + TB - 1) / TB;
    const int n4  = n / 4;
    const int e4  = e / 4;
    const int ge4 = (e4 + TB - 1) / TB;
    const int gp  = (n * 2 + TB - 1) / TB;
    const int nb  = (n + SCAN_TB - 1) / SCAN_TB;

    // CSR build
    k_zero <<<(n4 + TB - 1) / TB, TB>>>(n4);
    k_count<<<ge4, TB>>>(col, e4);
    k_scanA<<<nb,  SCAN_TB>>>(n, nb);
    k_scanC<<<gn,  TB>>>(n);
    k_fill <<<ge4, TB>>>(row, col, e4);

    // layer 1 (+ fused layer-2 transform)
    k_mm1       <<<gn, TB>>>(x, W1, n);
    k_gather_mid<<<gp, TB>>>(W2, b1, n);

    // layer 2 (+ fused readout)
    k_gather_final<<<gp, TB>>>(b2, Wl, bl, out, n);
}